// round 1
// baseline (speedup 1.0000x reference)
#include <cuda_runtime.h>

// Problem dims (fixed by the reference): x is (B=8, T=2048, F=128) float32.
#define BB 8
#define TT 2048
#define FF 128
#define NN (BB * TT * FF)           // 2,097,152
#define STRIDE_B (TT * FF)          // 262144
#define STRIDE_T (FF)               // 128

#define TAU_F (1.0f / 6.0f)
#define NITER 29                    // MAX_ITERS - 1 scan steps

// Scratch: dual field p (3 components) and the "out" intermediate.
// __device__ globals — no runtime allocation (harness rule).
__device__ float g_p0[NN];
__device__ float g_p1[NN];
__device__ float g_p2[NN];
__device__ float g_outbuf[NN];

// ---------------------------------------------------------------------------
// K0: zero the dual variable p (must happen every kernel_launch call so the
// graph replays deterministically).
// ---------------------------------------------------------------------------
__global__ void k_zero_p() {
    int idx = blockIdx.x * blockDim.x + threadIdx.x;
    if (idx >= NN) return;
    g_p0[idx] = 0.0f;
    g_p1[idx] = 0.0f;
    g_p2[idx] = 0.0f;
}

// ---------------------------------------------------------------------------
// K1: out = img + div(p)
//   div(p)[v] = sum_ax ( (v_ax>0 ? p[ax][v - e_ax] : 0) - p[ax][v] )
// ---------------------------------------------------------------------------
__global__ void k_compute_out(const float* __restrict__ img) {
    int idx = blockIdx.x * blockDim.x + threadIdx.x;
    if (idx >= NN) return;
    int f = idx & (FF - 1);
    int t = (idx >> 7) & (TT - 1);
    int b = idx >> 18;

    float d = 0.0f;
    d -= g_p0[idx];
    if (b > 0) d += g_p0[idx - STRIDE_B];
    d -= g_p1[idx];
    if (t > 0) d += g_p1[idx - STRIDE_T];
    d -= g_p2[idx];
    if (f > 0) d += g_p2[idx - 1];

    g_outbuf[idx] = img[idx] + d;
}

// ---------------------------------------------------------------------------
// K2: g[ax] = forward diff of out (0 at last slice); p updated in place:
//   norm  = sqrt(sum g^2)
//   denom = norm * (tau/weight) + 1
//   p     = (p - tau*g) / denom
// In-place on p is safe: neighbors are only read from g_outbuf.
// ---------------------------------------------------------------------------
__global__ void k_update_p(const float* __restrict__ lam) {
    int idx = blockIdx.x * blockDim.x + threadIdx.x;
    if (idx >= NN) return;
    int f = idx & (FF - 1);
    int t = (idx >> 7) & (TT - 1);
    int b = idx >> 18;

    float tw = TAU_F / lam[0];

    float o = g_outbuf[idx];
    float gb = (b < BB - 1) ? (g_outbuf[idx + STRIDE_B] - o) : 0.0f;
    float gt = (t < TT - 1) ? (g_outbuf[idx + STRIDE_T] - o) : 0.0f;
    float gf = (f < FF - 1) ? (g_outbuf[idx + 1] - o) : 0.0f;

    float norm = sqrtf(gb * gb + gt * gt + gf * gf);
    float denom = norm * tw + 1.0f;
    float inv = 1.0f / denom;

    g_p0[idx] = (g_p0[idx] - TAU_F * gb) * inv;
    g_p1[idx] = (g_p1[idx] - TAU_F * gt) * inv;
    g_p2[idx] = (g_p2[idx] - TAU_F * gf) * inv;
}

// ---------------------------------------------------------------------------
// K3: final output = img + div(p) + bias[f]
// ---------------------------------------------------------------------------
__global__ void k_final(const float* __restrict__ img,
                        const float* __restrict__ bias,
                        float* __restrict__ out) {
    int idx = blockIdx.x * blockDim.x + threadIdx.x;
    if (idx >= NN) return;
    int f = idx & (FF - 1);
    int t = (idx >> 7) & (TT - 1);
    int b = idx >> 18;

    float d = 0.0f;
    d -= g_p0[idx];
    if (b > 0) d += g_p0[idx - STRIDE_B];
    d -= g_p1[idx];
    if (t > 0) d += g_p1[idx - STRIDE_T];
    d -= g_p2[idx];
    if (f > 0) d += g_p2[idx - 1];

    out[idx] = img[idx] + d + bias[f];
}

extern "C" void kernel_launch(void* const* d_in, const int* in_sizes, int n_in,
                              void* d_out, int out_size) {
    const float* x   = (const float*)d_in[0];   // (8, 2048, 128)
    const float* lam = (const float*)d_in[1];   // (1, 1) scalar weight
    const float* b   = (const float*)d_in[2];   // (1, 1, 128)
    float* out = (float*)d_out;

    const int threads = 256;
    const int blocks = (NN + threads - 1) / threads;

    k_zero_p<<<blocks, threads>>>();
    for (int it = 0; it < NITER; ++it) {
        k_compute_out<<<blocks, threads>>>(x);
        k_update_p<<<blocks, threads>>>(lam);
    }
    k_final<<<blocks, threads>>>(x, b, out);
}

// round 2
// speedup vs baseline: 1.3636x; 1.3636x over previous
#include <cuda_runtime.h>

// Problem dims (fixed): x is (B=8, T=2048, F=128) float32.
#define BB 8
#define TT 2048
#define FF 128
#define NN (BB * TT * FF)           // 2,097,152
#define SB (TT * FF)                // 262144 (stride along B)
#define ST (FF)                     // 128    (stride along T)

#define TAU_F (1.0f / 6.0f)
#define NFUSED 28                   // updates #2..#29 (update #1 is k_first)

// Ping-pong dual-variable buffers (no runtime allocation allowed).
__device__ float g_pa0[NN], g_pa1[NN], g_pa2[NN];
__device__ float g_pb0[NN], g_pb1[NN], g_pb2[NN];

// out(site) = img[site] + div(p)[site]
//   div(p)[v] = sum_ax ( (v_ax>0 ? p[ax][v-e_ax] : 0) - p[ax][v] )
__device__ __forceinline__ float outv(const float* __restrict__ q0,
                                      const float* __restrict__ q1,
                                      const float* __restrict__ q2,
                                      const float* __restrict__ img,
                                      int idx, int b, int t, int f) {
    float d = img[idx] - q0[idx] - q1[idx] - q2[idx];
    if (b > 0) d += q0[idx - SB];
    if (t > 0) d += q1[idx - ST];
    if (f > 0) d += q2[idx - 1];
    return d;
}

// ---------------------------------------------------------------------------
// First p-update: p=0 => out = img, g = grad(img).  Writes pA.
// ---------------------------------------------------------------------------
__global__ void k_first(const float* __restrict__ img,
                        const float* __restrict__ lam) {
    int idx = blockIdx.x * blockDim.x + threadIdx.x;
    if (idx >= NN) return;
    int f = idx & (FF - 1);
    int t = (idx >> 7) & (TT - 1);
    int b = idx >> 18;

    float o  = img[idx];
    float gb = (b < BB - 1) ? (img[idx + SB] - o) : 0.0f;
    float gt = (t < TT - 1) ? (img[idx + ST] - o) : 0.0f;
    float gf = (f < FF - 1) ? (img[idx + 1] - o) : 0.0f;

    float tw   = TAU_F / lam[0];
    float norm = sqrtf(gb * gb + gt * gt + gf * gf);
    float inv  = 1.0f / (norm * tw + 1.0f);

    g_pa0[idx] = (-TAU_F * gb) * inv;
    g_pa1[idx] = (-TAU_F * gt) * inv;
    g_pa2[idx] = (-TAU_F * gf) * inv;
}

// ---------------------------------------------------------------------------
// Fused Chambolle step: reads p_in, writes p_out (double-buffered).
// Recomputes out() at the 4 sites needed for the forward gradient; neighbor
// loads overlap across threads -> L1/L2 hits.
// ---------------------------------------------------------------------------
template <bool A2B>
__global__ void k_fused(const float* __restrict__ img,
                        const float* __restrict__ lam) {
    const float* __restrict__ q0 = A2B ? g_pa0 : g_pb0;
    const float* __restrict__ q1 = A2B ? g_pa1 : g_pb1;
    const float* __restrict__ q2 = A2B ? g_pa2 : g_pb2;
    float* __restrict__ r0 = A2B ? g_pb0 : g_pa0;
    float* __restrict__ r1 = A2B ? g_pb1 : g_pa1;
    float* __restrict__ r2 = A2B ? g_pb2 : g_pa2;

    int idx = blockIdx.x * blockDim.x + threadIdx.x;
    if (idx >= NN) return;
    int f = idx & (FF - 1);
    int t = (idx >> 7) & (TT - 1);
    int b = idx >> 18;

    float o = outv(q0, q1, q2, img, idx, b, t, f);

    float gb = 0.0f, gt = 0.0f, gf = 0.0f;
    if (b < BB - 1) gb = outv(q0, q1, q2, img, idx + SB, b + 1, t, f) - o;
    if (t < TT - 1) gt = outv(q0, q1, q2, img, idx + ST, b, t + 1, f) - o;
    if (f < FF - 1) gf = outv(q0, q1, q2, img, idx + 1, b, t, f + 1) - o;

    float tw   = TAU_F / lam[0];
    float norm = sqrtf(gb * gb + gt * gt + gf * gf);
    float inv  = 1.0f / (norm * tw + 1.0f);

    r0[idx] = (q0[idx] - TAU_F * gb) * inv;
    r1[idx] = (q1[idx] - TAU_F * gt) * inv;
    r2[idx] = (q2[idx] - TAU_F * gf) * inv;
}

// ---------------------------------------------------------------------------
// Final: out = img + div(pA) + bias[f]
// ---------------------------------------------------------------------------
__global__ void k_final(const float* __restrict__ img,
                        const float* __restrict__ bias,
                        float* __restrict__ out) {
    int idx = blockIdx.x * blockDim.x + threadIdx.x;
    if (idx >= NN) return;
    int f = idx & (FF - 1);
    int t = (idx >> 7) & (TT - 1);
    int b = idx >> 18;

    float d = -g_pa0[idx] - g_pa1[idx] - g_pa2[idx];
    if (b > 0) d += g_pa0[idx - SB];
    if (t > 0) d += g_pa1[idx - ST];
    if (f > 0) d += g_pa2[idx - 1];

    out[idx] = img[idx] + d + bias[f];
}

extern "C" void kernel_launch(void* const* d_in, const int* in_sizes, int n_in,
                              void* d_out, int out_size) {
    const float* x   = (const float*)d_in[0];   // (8, 2048, 128)
    const float* lam = (const float*)d_in[1];   // (1, 1)
    const float* b   = (const float*)d_in[2];   // (1, 1, 128)
    float* out = (float*)d_out;

    const int threads = 256;
    const int blocks = (NN + threads - 1) / threads;

    // Update #1 (p starts at zero): write pA directly from img.
    k_first<<<blocks, threads>>>(x, lam);

    // Updates #2..#29: ping-pong pA <-> pB. 28 steps (even) ends back in pA.
    for (int it = 0; it < NFUSED; ++it) {
        if ((it & 1) == 0)
            k_fused<true><<<blocks, threads>>>(x, lam);   // A -> B
        else
            k_fused<false><<<blocks, threads>>>(x, lam);  // B -> A
    }

    k_final<<<blocks, threads>>>(x, b, out);
}

// round 3
// speedup vs baseline: 1.9823x; 1.4537x over previous
#include <cuda_runtime.h>

// Dims fixed by the reference: x is (B=8, T=2048, F=128) float32.
#define BB 8
#define TT 2048
#define FF 128
#define NN (BB * TT * FF)           // 2,097,152
#define SB (TT * FF)                // 262144
#define ST (FF)                     // 128

#define TAU_F (1.0f / 6.0f)
#define NFUSED 28                   // updates #2..#29 (update #1 is k_first)

#define TTILE 4                     // T-rows per block tile
#define NWARP 8
#define NTHREADS (NWARP * 32)       // 256
#define F4 (FF / 4)                 // 32 float4 per row == one warp

// Ping-pong dual buffers (no runtime allocation allowed).
__device__ float g_pa0[NN], g_pa1[NN], g_pa2[NN];
__device__ float g_pb0[NN], g_pb1[NN], g_pb2[NN];

__device__ __forceinline__ float4 ld4(const float* __restrict__ p, int idx) {
    return *reinterpret_cast<const float4*>(p + idx);
}
__device__ __forceinline__ void st4(float* __restrict__ p, int idx, float4 v) {
    *reinterpret_cast<float4*>(p + idx) = v;
}
__device__ __forceinline__ float4 f4sub(float4 a, float4 b) {
    return make_float4(a.x - b.x, a.y - b.y, a.z - b.z, a.w - b.w);
}
__device__ __forceinline__ float4 f4add(float4 a, float4 b) {
    return make_float4(a.x + b.x, a.y + b.y, a.z + b.z, a.w + b.w);
}

// ---------------------------------------------------------------------------
// k_first: p = 0  =>  out = img, g = grad(img). Writes pA. One float4/thread.
// One warp covers one (b,t) row: lane == f4 index.
// ---------------------------------------------------------------------------
__global__ __launch_bounds__(NTHREADS)
void k_first(const float* __restrict__ img, const float* __restrict__ lam) {
    int tid = blockIdx.x * blockDim.x + threadIdx.x;   // float4 index
    if (tid >= NN / 4) return;
    int lane = tid & 31;                               // == f4
    int t = (tid >> 5) & (TT - 1);
    int b = tid >> 16;
    int idx = tid * 4;

    float4 o = ld4(img, idx);
    float4 gb = make_float4(0, 0, 0, 0), gt = make_float4(0, 0, 0, 0), gf;
    if (b < BB - 1) gb = f4sub(ld4(img, idx + SB), o);
    if (t < TT - 1) gt = f4sub(ld4(img, idx + ST), o);
    float nx = __shfl_down_sync(0xffffffffu, o.x, 1);
    gf.x = o.y - o.x; gf.y = o.z - o.y; gf.z = o.w - o.z;
    gf.w = (lane < 31) ? (nx - o.w) : 0.0f;            // f==127 boundary

    float tw = TAU_F / lam[0];
    float4 r0, r1, r2;
#define FIRST_UPD(c)                                                     \
    { float n = sqrtf(gb.c * gb.c + gt.c * gt.c + gf.c * gf.c);          \
      float inv = 1.0f / (n * tw + 1.0f);                                \
      r0.c = (-TAU_F * gb.c) * inv;                                      \
      r1.c = (-TAU_F * gt.c) * inv;                                      \
      r2.c = (-TAU_F * gf.c) * inv; }
    FIRST_UPD(x) FIRST_UPD(y) FIRST_UPD(z) FIRST_UPD(w)
#undef FIRST_UPD
    st4(g_pa0, idx, r0);
    st4(g_pa1, idx, r1);
    st4(g_pa2, idx, r2);
}

// ---------------------------------------------------------------------------
// k_fused: one Chambolle step. Block tile = (all 8 b) x (TTILE t-rows) x (F).
// Phase A: compute out = img + div(p_in) into smem for TTILE+1 t-rows.
// Phase B: gradients from smem, update p_out. Ping-pong p buffers.
// ---------------------------------------------------------------------------
template <bool A2B>
__global__ __launch_bounds__(NTHREADS)
void k_fused(const float* __restrict__ img, const float* __restrict__ lam) {
    const float* __restrict__ q0 = A2B ? g_pa0 : g_pb0;
    const float* __restrict__ q1 = A2B ? g_pa1 : g_pb1;
    const float* __restrict__ q2 = A2B ? g_pa2 : g_pb2;
    float* __restrict__ r0 = A2B ? g_pb0 : g_pa0;
    float* __restrict__ r1 = A2B ? g_pb1 : g_pa1;
    float* __restrict__ r2 = A2B ? g_pb2 : g_pa2;

    __shared__ float4 s_out[BB][TTILE + 1][F4];        // 8*5*32*16 = 20 KB

    int warp = threadIdx.x >> 5;
    int lane = threadIdx.x & 31;                        // == f4
    int t0 = blockIdx.x * TTILE;
    float tw = TAU_F / lam[0];

    // Phase A: 8*(TTILE+1) = 40 rows, 5 per warp. Row validity warp-uniform.
    for (int r = warp; r < BB * (TTILE + 1); r += NWARP) {
        int b = r / (TTILE + 1);
        int trow = r - b * (TTILE + 1);
        int t = t0 + trow;
        if (t < TT) {
            int idx = b * SB + t * ST + lane * 4;
            float4 d = ld4(img, idx);
            float4 a0 = ld4(q0, idx);
            float4 a1 = ld4(q1, idx);
            float4 a2 = ld4(q2, idx);
            d = f4sub(f4sub(f4sub(d, a0), a1), a2);
            if (b > 0) d = f4add(d, ld4(q0, idx - SB));
            if (t > 0) d = f4add(d, ld4(q1, idx - ST));
            // + p2[f-1]: within-vector for y,z,w; lane-1's .w for x (0 at f==0)
            float prevw = __shfl_up_sync(0xffffffffu, a2.w, 1);
            if (lane > 0) d.x += prevw;
            d.y += a2.x; d.z += a2.y; d.w += a2.z;
            s_out[b][trow][lane] = d;
        }
    }
    __syncthreads();

    // Phase B: 8*TTILE = 32 rows, 4 per warp.
    for (int r = warp; r < BB * TTILE; r += NWARP) {
        int b = r >> 2;                                 // r / TTILE
        int trow = r & (TTILE - 1);
        int t = t0 + trow;
        int idx = b * SB + t * ST + lane * 4;

        float4 o = s_out[b][trow][lane];
        float4 gb = make_float4(0, 0, 0, 0), gt = make_float4(0, 0, 0, 0), gf;
        if (b < BB - 1) gb = f4sub(s_out[b + 1][trow][lane], o);
        if (t < TT - 1) gt = f4sub(s_out[b][trow + 1][lane], o);
        float nx = __shfl_down_sync(0xffffffffu, o.x, 1);
        gf.x = o.y - o.x; gf.y = o.z - o.y; gf.z = o.w - o.z;
        gf.w = (lane < 31) ? (nx - o.w) : 0.0f;

        float4 a0 = ld4(q0, idx);
        float4 a1 = ld4(q1, idx);
        float4 a2 = ld4(q2, idx);
        float4 o0, o1, o2;
#define UPD(c)                                                            \
        { float n = sqrtf(gb.c * gb.c + gt.c * gt.c + gf.c * gf.c);       \
          float inv = 1.0f / (n * tw + 1.0f);                             \
          o0.c = (a0.c - TAU_F * gb.c) * inv;                             \
          o1.c = (a1.c - TAU_F * gt.c) * inv;                             \
          o2.c = (a2.c - TAU_F * gf.c) * inv; }
        UPD(x) UPD(y) UPD(z) UPD(w)
#undef UPD
        st4(r0, idx, o0);
        st4(r1, idx, o1);
        st4(r2, idx, o2);
    }
}

// ---------------------------------------------------------------------------
// k_final: out = img + div(pA) + bias[f]. One float4/thread.
// ---------------------------------------------------------------------------
__global__ __launch_bounds__(NTHREADS)
void k_final(const float* __restrict__ img, const float* __restrict__ bias,
             float* __restrict__ out) {
    int tid = blockIdx.x * blockDim.x + threadIdx.x;
    if (tid >= NN / 4) return;
    int lane = tid & 31;                               // == f4
    int t = (tid >> 5) & (TT - 1);
    int b = tid >> 16;
    int idx = tid * 4;

    float4 d = ld4(img, idx);
    float4 a0 = ld4(g_pa0, idx);
    float4 a1 = ld4(g_pa1, idx);
    float4 a2 = ld4(g_pa2, idx);
    d = f4sub(f4sub(f4sub(d, a0), a1), a2);
    if (b > 0) d = f4add(d, ld4(g_pa0, idx - SB));
    if (t > 0) d = f4add(d, ld4(g_pa1, idx - ST));
    float prevw = __shfl_up_sync(0xffffffffu, a2.w, 1);
    if (lane > 0) d.x += prevw;
    d.y += a2.x; d.z += a2.y; d.w += a2.z;

    d = f4add(d, ld4(bias, lane * 4));
    st4(out, idx, d);
}

extern "C" void kernel_launch(void* const* d_in, const int* in_sizes, int n_in,
                              void* d_out, int out_size) {
    const float* x   = (const float*)d_in[0];   // (8, 2048, 128)
    const float* lam = (const float*)d_in[1];   // (1, 1)
    const float* b   = (const float*)d_in[2];   // (1, 1, 128)
    float* out = (float*)d_out;

    const int vblocks = (NN / 4 + NTHREADS - 1) / NTHREADS;   // 2048
    const int fblocks = TT / TTILE;                           // 512

    k_first<<<vblocks, NTHREADS>>>(x, lam);

    for (int it = 0; it < NFUSED; ++it) {
        if ((it & 1) == 0)
            k_fused<true><<<fblocks, NTHREADS>>>(x, lam);   // A -> B
        else
            k_fused<false><<<fblocks, NTHREADS>>>(x, lam);  // B -> A
    }

    k_final<<<vblocks, NTHREADS>>>(x, b, out);
}